// round 5
// baseline (speedup 1.0000x reference)
#include <cuda_runtime.h>
#include <math.h>
#include <stdint.h>

// Problem dims
#define BATCH 8
#define ENS   16
#define NCIN  64
#define NCH   64
#define HW    4096
#define NBI   (BATCH*ENS)          // 128
#define NELEM ((size_t)NBI*NCH*HW) // 33,554,432

// Scratch (static device arrays -- allocation-free)
__device__ float g_V[NELEM];
__device__ float g_K[NELEM];
__device__ float g_Q[NELEM];
__device__ float g_Wgt[BATCH*NCH*ENS*ENS]; // softmaxed weights [b,c,i,j]

__device__ __forceinline__ float selu_f(float x) {
    const float scale = 1.0507009873554805f;
    const float alpha = 1.6732632423543772f;
    return x > 0.f ? scale * x : scale * alpha * expm1f(x);
}

__device__ __forceinline__ uint32_t smem_u32(const void* p) {
    return (uint32_t)__cvta_generic_to_shared(p);
}
__device__ __forceinline__ float to_tf32(float x) {
    float r;
    asm("cvt.rna.tf32.f32 %0, %1;" : "=f"(r) : "f"(x));
    return r;
}
__device__ __forceinline__ void cp16(void* dst_smem, const void* src) {
    uint32_t d = smem_u32(dst_smem);
    asm volatile("cp.async.cg.shared.global [%0], [%1], 16;" :: "r"(d), "l"(src));
}
#define CP_COMMIT()  asm volatile("cp.async.commit_group;" ::: "memory")
#define CP_WAIT(n)   asm volatile("cp.async.wait_group %0;" :: "n"(n) : "memory")

// Warp-level tf32 MMA (baseline PTX, works on sm_103 non-'a' target)
__device__ __forceinline__ void mma_tf32(float* c,
                                         uint32_t a0, uint32_t a1, uint32_t a2, uint32_t a3,
                                         uint32_t b0, uint32_t b1)
{
    asm volatile(
        "mma.sync.aligned.m16n8k8.row.col.f32.tf32.tf32.f32 "
        "{%0,%1,%2,%3}, {%4,%5,%6,%7}, {%8,%9}, {%0,%1,%2,%3};"
        : "+f"(c[0]), "+f"(c[1]), "+f"(c[2]), "+f"(c[3])
        : "r"(a0), "r"(a1), "r"(a2), "r"(a3), "r"(b0), "r"(b1));
}

// ===========================================================================
// Kernel 1: fused 3-conv via 3xTF32 mma.sync.
// Per (b,i): Out[192 ch, 4096 hw] = W3[192,64] @ X[64,4096]
// ch 0..63 -> V(+bias), 64..127 -> K(+bias,selu), 128..191 -> Q(+bias,selu)
// CTA: 256 thr (8 warps, 4m x 2n), tile 192 x 128 hw, 4 tiles per CTA.
// ===========================================================================
#define TPC       4
#define A_STRIDE  76    // floats; conflict-free A-fragment LDS
#define X_STRIDE  136   // floats; conflict-free B-fragment LDS

// SMEM float offsets
#define OFF_AH    0
#define OFF_AL    (192*A_STRIDE)                 // 14592
#define OFF_X0    (2*192*A_STRIDE)               // 29184
#define OFF_X1    (OFF_X0 + 64*X_STRIDE)         // +8704
#define OFF_BIAS  (OFF_X0 + 2*64*X_STRIDE)
#define SMEM_FLOATS (OFF_BIAS + 192)
#define SMEM_BYTES  (SMEM_FLOATS*4)

__global__ __launch_bounds__(256, 1)
void conv3_mma_kernel(const float* __restrict__ x,
                      const float* __restrict__ Wv, const float* __restrict__ bv,
                      const float* __restrict__ Wk, const float* __restrict__ bk,
                      const float* __restrict__ Wq, const float* __restrict__ bq)
{
    extern __shared__ float smem[];
    float* Ah = smem + OFF_AH;
    float* Al = smem + OFF_AL;
    float* sbias = smem + OFF_BIAS;

    const int tid  = threadIdx.x;
    const int wid  = tid >> 5;
    const int lane = tid & 31;
    const int g    = lane >> 2;     // groupID
    const int tig  = lane & 3;      // threadID_in_group

    const int bi = blockIdx.x;      // 0..127
    const int tg = blockIdx.y;      // 0..7
    const float* xb = x + (size_t)bi * NCIN * HW;

    // ---- stage first X tile ----
    {
        const int hw0 = tg * TPC * 128;
        float* X0 = smem + OFF_X0;
        #pragma unroll
        for (int j = 0; j < 8; j++) {
            int idx = tid + j * 256;           // 2048 float4s
            int cin = idx >> 5, c4 = idx & 31;
            cp16(&X0[cin * X_STRIDE + c4 * 4],
                 xb + (size_t)cin * HW + hw0 + c4 * 4);
        }
        CP_COMMIT();
    }

    // ---- W3 -> tf32 hi/lo in SMEM; bias ----
    if (tid < 192) {
        sbias[tid] = tid < 64 ? bv[tid] : (tid < 128 ? bk[tid - 64] : bq[tid - 128]);
    }
    for (int idx = tid; idx < 192 * 64; idx += 256) {
        int n = idx >> 6, k = idx & 63;
        float w = n < 64 ? Wv[n * NCIN + k]
                : n < 128 ? Wk[(n - 64) * NCIN + k]
                          : Wq[(n - 128) * NCIN + k];
        float h = to_tf32(w);
        float l = to_tf32(w - h);
        Ah[n * A_STRIDE + k] = h;
        Al[n * A_STRIDE + k] = l;
    }
    __syncthreads();

    const int mrow0 = (wid & 3) * 48;   // warp channel-rows base
    const int ncol0 = (wid >> 2) * 64;  // warp hw-cols base (within 128)

    for (int t = 0; t < TPC; t++) {
        const int hw0 = (tg * TPC + t) * 128;

        // prefetch next X tile
        if (t + 1 < TPC) {
            const int hwn = hw0 + 128;
            float* nb = smem + (((t + 1) & 1) ? OFF_X1 : OFF_X0);
            #pragma unroll
            for (int j = 0; j < 8; j++) {
                int idx = tid + j * 256;
                int cin = idx >> 5, c4 = idx & 31;
                cp16(&nb[cin * X_STRIDE + c4 * 4],
                     xb + (size_t)cin * HW + hwn + c4 * 4);
            }
            CP_COMMIT();
            CP_WAIT(1);
        } else {
            CP_WAIT(0);
        }
        __syncthreads();   // X(t) visible to all warps

        const float* Xs = smem + ((t & 1) ? OFF_X1 : OFF_X0);

        float acc[3][8][4];
        #pragma unroll
        for (int ms = 0; ms < 3; ms++)
            #pragma unroll
            for (int ns = 0; ns < 8; ns++)
                #pragma unroll
                for (int q = 0; q < 4; q++) acc[ms][ns][q] = 0.f;

        #pragma unroll
        for (int ks = 0; ks < 8; ks++) {
            const int k0 = ks * 8;

            // B fragments: X[k][hw], convert fp32 -> tf32 hi/lo in regs
            uint32_t bh[8][2], bl[8][2];
            #pragma unroll
            for (int ns = 0; ns < 8; ns++) {
                float f0 = Xs[(k0 + tig) * X_STRIDE + ncol0 + ns * 8 + g];
                float f1 = Xs[(k0 + tig + 4) * X_STRIDE + ncol0 + ns * 8 + g];
                float h0 = to_tf32(f0), h1 = to_tf32(f1);
                bh[ns][0] = __float_as_uint(h0);
                bh[ns][1] = __float_as_uint(h1);
                bl[ns][0] = __float_as_uint(to_tf32(f0 - h0));
                bl[ns][1] = __float_as_uint(to_tf32(f1 - h1));
            }

            #pragma unroll
            for (int ms = 0; ms < 3; ms++) {
                const int rb = mrow0 + ms * 16;
                uint32_t ah0 = __float_as_uint(Ah[(rb + g) * A_STRIDE + k0 + tig]);
                uint32_t ah1 = __float_as_uint(Ah[(rb + 8 + g) * A_STRIDE + k0 + tig]);
                uint32_t ah2 = __float_as_uint(Ah[(rb + g) * A_STRIDE + k0 + tig + 4]);
                uint32_t ah3 = __float_as_uint(Ah[(rb + 8 + g) * A_STRIDE + k0 + tig + 4]);
                uint32_t al0 = __float_as_uint(Al[(rb + g) * A_STRIDE + k0 + tig]);
                uint32_t al1 = __float_as_uint(Al[(rb + 8 + g) * A_STRIDE + k0 + tig]);
                uint32_t al2 = __float_as_uint(Al[(rb + g) * A_STRIDE + k0 + tig + 4]);
                uint32_t al3 = __float_as_uint(Al[(rb + 8 + g) * A_STRIDE + k0 + tig + 4]);

                #pragma unroll
                for (int ns = 0; ns < 8; ns++) {
                    mma_tf32(acc[ms][ns], ah0, ah1, ah2, ah3, bh[ns][0], bh[ns][1]);
                    mma_tf32(acc[ms][ns], ah0, ah1, ah2, ah3, bl[ns][0], bl[ns][1]);
                    mma_tf32(acc[ms][ns], al0, al1, al2, al3, bh[ns][0], bh[ns][1]);
                }
            }
        }

        // ---- epilogue: bias (+selu), float2 stores ----
        float* baseV = g_V + (size_t)bi * NCH * HW + hw0;
        float* baseK = g_K + (size_t)bi * NCH * HW + hw0;
        float* baseQ = g_Q + (size_t)bi * NCH * HW + hw0;
        #pragma unroll
        for (int ms = 0; ms < 3; ms++) {
            #pragma unroll
            for (int half = 0; half < 2; half++) {
                const int c = mrow0 + ms * 16 + g + half * 8;
                const float bb = sbias[c];
                #pragma unroll
                for (int ns = 0; ns < 8; ns++) {
                    const int col = ncol0 + ns * 8 + tig * 2;
                    float v0 = acc[ms][ns][half * 2 + 0] + bb;
                    float v1 = acc[ms][ns][half * 2 + 1] + bb;
                    float2 o;
                    if (c < 64) {
                        o.x = v0; o.y = v1;
                        *(float2*)&baseV[(size_t)c * HW + col] = o;
                    } else if (c < 128) {
                        o.x = selu_f(v0); o.y = selu_f(v1);
                        *(float2*)&baseK[(size_t)(c - 64) * HW + col] = o;
                    } else {
                        o.x = selu_f(v0); o.y = selu_f(v1);
                        *(float2*)&baseQ[(size_t)(c - 128) * HW + col] = o;
                    }
                }
            }
        }
        __syncthreads();   // protect Xs[t&1] before it is re-staged at t+1
    }
}

// ---------------------------------------------------------------------------
// Kernel 2: gram + softmax.  One block per (b,c).
// ---------------------------------------------------------------------------
__global__ __launch_bounds__(128)
void gram_softmax_kernel()
{
    const int c = blockIdx.x;
    const int b = blockIdx.y;
    const int tid  = threadIdx.x;
    const int jg   = tid >> 5;
    const int lane = tid & 31;

    const float* Kb = g_K + ((size_t)b * ENS * NCH + c) * HW;
    const float* Qb = g_Q + ((size_t)b * ENS * NCH + c) * HW;

    float acc[16][4];
    #pragma unroll
    for (int i = 0; i < 16; i++)
        #pragma unroll
        for (int jj = 0; jj < 4; jj++) acc[i][jj] = 0.f;

    for (int it = 0; it < HW / 128; it++) {
        const int pos = (it * 32 + lane) * 4;
        float4 q[4];
        #pragma unroll
        for (int jj = 0; jj < 4; jj++) {
            int j = jg * 4 + jj;
            q[jj] = *(const float4*)&Qb[(size_t)j * NCH * HW + pos];
        }
        #pragma unroll
        for (int i = 0; i < 16; i++) {
            float4 k4 = *(const float4*)&Kb[(size_t)i * NCH * HW + pos];
            #pragma unroll
            for (int jj = 0; jj < 4; jj++) {
                acc[i][jj] += k4.x * q[jj].x + k4.y * q[jj].y
                            + k4.z * q[jj].z + k4.w * q[jj].w;
            }
        }
    }

    __shared__ float sdots[16][16];
    #pragma unroll
    for (int i = 0; i < 16; i++)
        #pragma unroll
        for (int jj = 0; jj < 4; jj++) {
            float v = acc[i][jj];
            #pragma unroll
            for (int off = 16; off > 0; off >>= 1)
                v += __shfl_xor_sync(0xffffffffu, v, off);
            if (lane == 0) sdots[i][jg * 4 + jj] = v;
        }
    __syncthreads();

    if (tid < 16) {
        const int j = tid;
        float m = -INFINITY;
        #pragma unroll
        for (int i = 0; i < 16; i++) m = fmaxf(m, sdots[i][j]);
        float e[16], s = 0.f;
        #pragma unroll
        for (int i = 0; i < 16; i++) { e[i] = expf(sdots[i][j] - m); s += e[i]; }
        const float inv = 1.f / s;
        #pragma unroll
        for (int i = 0; i < 16; i++)
            g_Wgt[(((size_t)b * NCH + c) * ENS + i) * ENS + j] = e[i] * inv;
    }
}

// ---------------------------------------------------------------------------
// Kernel 3: mix + selu.  (mean-centering cancels via softmax)
// ---------------------------------------------------------------------------
__global__ __launch_bounds__(256)
void mix_kernel(float* __restrict__ out)
{
    const int tile = blockIdx.x;
    const int c    = blockIdx.y;
    const int b    = blockIdx.z;
    const int tid  = threadIdx.x;

    __shared__ float ws[16][16];
    ws[tid >> 4][tid & 15] = g_Wgt[((size_t)b * NCH + c) * 256 + tid];
    __syncthreads();

    const int pos = tile * 512 + tid * 2;
    const float* Vb = g_V + ((size_t)b * ENS * NCH + c) * HW + pos;
    float*       ob = out + ((size_t)b * ENS * NCH + c) * HW + pos;

    float2 v[16];
    #pragma unroll
    for (int i = 0; i < 16; i++)
        v[i] = *(const float2*)&Vb[(size_t)i * NCH * HW];

    #pragma unroll
    for (int j = 0; j < 16; j++) {
        float sx = 0.f, sy = 0.f;
        #pragma unroll
        for (int i = 0; i < 16; i++) {
            float w = ws[i][j];
            sx += w * v[i].x;
            sy += w * v[i].y;
        }
        float2 o; o.x = selu_f(sx); o.y = selu_f(sy);
        *(float2*)&ob[(size_t)j * NCH * HW] = o;
    }
}

// ---------------------------------------------------------------------------
extern "C" void kernel_launch(void* const* d_in, const int* in_sizes, int n_in,
                              void* d_out, int out_size)
{
    const float* x  = (const float*)d_in[0];
    const float* Wv = (const float*)d_in[1];
    const float* bv = (const float*)d_in[2];
    const float* Wk = (const float*)d_in[3];
    const float* bk = (const float*)d_in[4];
    const float* Wq = (const float*)d_in[5];
    const float* bq = (const float*)d_in[6];
    float* out = (float*)d_out;

    cudaFuncSetAttribute(conv3_mma_kernel,
                         cudaFuncAttributeMaxDynamicSharedMemorySize, SMEM_BYTES);

    dim3 g1(NBI, (HW / 128) / TPC);   // (128, 8)
    conv3_mma_kernel<<<g1, 256, SMEM_BYTES>>>(x, Wv, bv, Wk, bk, Wq, bq);

    dim3 g2(NCH, BATCH);
    gram_softmax_kernel<<<g2, 128>>>();

    dim3 g3(HW / 512, NCH, BATCH);
    mix_kernel<<<g3, 256>>>(out);
}

// round 7
// speedup vs baseline: 1.8424x; 1.8424x over previous
#include <cuda_runtime.h>
#include <cuda_fp16.h>
#include <math.h>
#include <stdint.h>
#include <string.h>

// Problem dims
#define BATCH 8
#define ENS   16
#define NCIN  64
#define NCH   64
#define HW    4096
#define NBI   (BATCH*ENS)          // 128
#define NELEM ((size_t)NBI*NCH*HW) // 33,554,432

// Scratch (static device arrays -- allocation-free)
__device__ float g_V[NELEM];
__device__ float g_K[NELEM];
__device__ float g_Q[NELEM];
__device__ float g_Wgt[BATCH*NCH*ENS*ENS]; // softmaxed weights [b,c,i,j]

__device__ __forceinline__ float selu_f(float x) {
    const float scale = 1.0507009873554805f;
    const float alpha = 1.6732632423543772f;
    return x > 0.f ? scale * x : scale * alpha * expm1f(x);
}

__device__ __forceinline__ uint32_t h2u(__half2 v) {
    uint32_t r;
    memcpy(&r, &v, sizeof(r));
    return r;
}

__device__ __forceinline__ uint32_t smem_u32(const void* p) {
    return (uint32_t)__cvta_generic_to_shared(p);
}
__device__ __forceinline__ void cp16(void* dst_smem, const void* src) {
    uint32_t d = smem_u32(dst_smem);
    asm volatile("cp.async.cg.shared.global [%0], [%1], 16;" :: "r"(d), "l"(src));
}
#define CP_COMMIT()  asm volatile("cp.async.commit_group;" ::: "memory")
#define CP_WAIT(n)   asm volatile("cp.async.wait_group %0;" :: "n"(n) : "memory")

// fp16 MMA m16n8k16 (baseline PTX, valid on sm_103 non-'a' target)
__device__ __forceinline__ void mma_f16(float* c,
                                        uint32_t a0, uint32_t a1, uint32_t a2, uint32_t a3,
                                        uint32_t b0, uint32_t b1)
{
    asm volatile(
        "mma.sync.aligned.m16n8k16.row.col.f32.f16.f16.f32 "
        "{%0,%1,%2,%3}, {%4,%5,%6,%7}, {%8,%9}, {%0,%1,%2,%3};"
        : "+f"(c[0]), "+f"(c[1]), "+f"(c[2]), "+f"(c[3])
        : "r"(a0), "r"(a1), "r"(a2), "r"(a3), "r"(b0), "r"(b1));
}

// ===========================================================================
// Kernel 1: fused 3-conv via FP16-split (2-way) mma.sync m16n8k16.
// Per (b,i): Out[192 ch, 4096 hw] = W3[192,64] @ X[64,4096]
// W = Wh + Wl, X = Xh + Xl (fp16 halves). D = Wh*Xh + Wh*Xl + Wl*Xh.
// ch 0..63 -> V(+bias), 64..127 -> K(+bias,selu), 128..191 -> Q(+bias,selu)
// CTA: 256 thr (8 warps, 4m x 2n), tile 192 x 128 hw, TPC hw-tiles per CTA.
// ===========================================================================
#define TPC        4
#define W_STRIDE   36    // half2 units per W row (32 kpairs + pad)
#define X_STRIDE   136   // half2 units per X kpair-row (128 cols + pad)
#define RAW_STRIDE 132   // float units per raw X row (128 + pad)

// SMEM byte offsets
#define OFF_WH    0                                  // 192*36*4   = 27648
#define OFF_WL    (OFF_WH   + 192*W_STRIDE*4)        // 27648
#define OFF_RAW0  (OFF_WL   + 192*W_STRIDE*4)        // 55296; 64*132*4 = 33792
#define OFF_RAW1  (OFF_RAW0 + 64*RAW_STRIDE*4)       // 89088
#define OFF_XH    (OFF_RAW1 + 64*RAW_STRIDE*4)       // 122880; 32*136*4 = 17408
#define OFF_XL    (OFF_XH   + 32*X_STRIDE*4)         // 140288
#define OFF_BIAS  (OFF_XL   + 32*X_STRIDE*4)         // 157696
#define SMEM_BYTES (OFF_BIAS + 192*4)                // 158464

__global__ __launch_bounds__(256, 1)
void conv3_mma_kernel(const float* __restrict__ x,
                      const float* __restrict__ Wv, const float* __restrict__ bv,
                      const float* __restrict__ Wk, const float* __restrict__ bk,
                      const float* __restrict__ Wq, const float* __restrict__ bq)
{
    extern __shared__ char smem[];
    __half2* Whs = (__half2*)(smem + OFF_WH);
    __half2* Wls = (__half2*)(smem + OFF_WL);
    __half2* Xh  = (__half2*)(smem + OFF_XH);
    __half2* Xl  = (__half2*)(smem + OFF_XL);
    float*   sbias = (float*)(smem + OFF_BIAS);
    float*   raw[2] = { (float*)(smem + OFF_RAW0), (float*)(smem + OFF_RAW1) };

    const int tid  = threadIdx.x;
    const int wid  = tid >> 5;
    const int lane = tid & 31;
    const int g    = lane >> 2;     // groupID
    const int tig  = lane & 3;      // threadID_in_group

    const int bi = blockIdx.x;      // 0..127
    const int tg = blockIdx.y;      // 0..7
    const float* xb = x + (size_t)bi * NCIN * HW;

    // ---- stage tile0 raw X via cp.async ----
    {
        const int hw0 = tg * TPC * 128;
        #pragma unroll
        for (int j = 0; j < 8; j++) {
            int idx = tid + j * 256;          // 2048 float4s
            int cin = idx >> 5, c4 = idx & 31;
            cp16(&raw[0][cin * RAW_STRIDE + c4 * 4],
                 xb + (size_t)cin * HW + hw0 + c4 * 4);
        }
        CP_COMMIT();
    }

    // ---- W3 -> fp16 hi/lo in SMEM (kpair-packed, row-major); bias ----
    if (tid < 192) {
        sbias[tid] = tid < 64 ? bv[tid] : (tid < 128 ? bk[tid - 64] : bq[tid - 128]);
    }
    for (int idx = tid; idx < 192 * 32; idx += 256) {
        int n = idx >> 5, kp = idx & 31;
        const float* Wsrc = n < 64 ? &Wv[n * NCIN] :
                            n < 128 ? &Wk[(n - 64) * NCIN] : &Wq[(n - 128) * NCIN];
        float w0 = Wsrc[kp * 2], w1 = Wsrc[kp * 2 + 1];
        __half2 h = __floats2half2_rn(w0, w1);
        __half2 l = __floats2half2_rn(w0 - __low2float(h), w1 - __high2float(h));
        Whs[n * W_STRIDE + kp] = h;
        Wls[n * W_STRIDE + kp] = l;
    }

    CP_WAIT(0);
    __syncthreads();

    // ---- convert raw tile0 -> Xh/Xl ----
    {
        const float* r0 = raw[0];
        #pragma unroll
        for (int j = 0; j < 4; j++) {
            int u = tid + j * 256;            // 1024 (kp, c4) units
            int kp = u >> 5, c4 = u & 31;
            float4 p0 = *(const float4*)&r0[(2 * kp) * RAW_STRIDE + c4 * 4];
            float4 p1 = *(const float4*)&r0[(2 * kp + 1) * RAW_STRIDE + c4 * 4];
            __half2 h0 = __floats2half2_rn(p0.x, p1.x);
            __half2 h1 = __floats2half2_rn(p0.y, p1.y);
            __half2 h2 = __floats2half2_rn(p0.z, p1.z);
            __half2 h3 = __floats2half2_rn(p0.w, p1.w);
            __half2 l0 = __floats2half2_rn(p0.x - __low2float(h0), p1.x - __high2float(h0));
            __half2 l1 = __floats2half2_rn(p0.y - __low2float(h1), p1.y - __high2float(h1));
            __half2 l2 = __floats2half2_rn(p0.z - __low2float(h2), p1.z - __high2float(h2));
            __half2 l3 = __floats2half2_rn(p0.w - __low2float(h3), p1.w - __high2float(h3));
            *(uint4*)&Xh[kp * X_STRIDE + c4 * 4] =
                make_uint4(h2u(h0), h2u(h1), h2u(h2), h2u(h3));
            *(uint4*)&Xl[kp * X_STRIDE + c4 * 4] =
                make_uint4(h2u(l0), h2u(l1), h2u(l2), h2u(l3));
        }
    }
    __syncthreads();

    const int mrow0 = (wid & 3) * 48;   // warp channel-rows base
    const int ncol0 = (wid >> 2) * 64;  // warp hw-cols base (within 128)

    for (int t = 0; t < TPC; t++) {
        const int hw0 = (tg * TPC + t) * 128;

        // prefetch next raw tile (overlaps with MMA below)
        if (t + 1 < TPC) {
            float* nb = raw[(t + 1) & 1];
            const int hwn = hw0 + 128;
            #pragma unroll
            for (int j = 0; j < 8; j++) {
                int idx = tid + j * 256;
                int cin = idx >> 5, c4 = idx & 31;
                cp16(&nb[cin * RAW_STRIDE + c4 * 4],
                     xb + (size_t)cin * HW + hwn + c4 * 4);
            }
            CP_COMMIT();
        }

        // ---- MMA: 4 ksteps (K=16) x 3 products ----
        float acc[3][8][4];
        #pragma unroll
        for (int ms = 0; ms < 3; ms++)
            #pragma unroll
            for (int ns = 0; ns < 8; ns++)
                #pragma unroll
                for (int q = 0; q < 4; q++) acc[ms][ns][q] = 0.f;

        #pragma unroll
        for (int ks = 0; ks < 4; ks++) {
            const int kb = ks * 8;
            uint32_t bh[8][2], bl[8][2];
            #pragma unroll
            for (int ns = 0; ns < 8; ns++) {
                const int col = ncol0 + ns * 8 + g;
                bh[ns][0] = *(const uint32_t*)&Xh[(kb + tig) * X_STRIDE + col];
                bh[ns][1] = *(const uint32_t*)&Xh[(kb + tig + 4) * X_STRIDE + col];
                bl[ns][0] = *(const uint32_t*)&Xl[(kb + tig) * X_STRIDE + col];
                bl[ns][1] = *(const uint32_t*)&Xl[(kb + tig + 4) * X_STRIDE + col];
            }
            #pragma unroll
            for (int ms = 0; ms < 3; ms++) {
                const int r0 = (mrow0 + ms * 16 + g) * W_STRIDE;
                const int r1 = (mrow0 + ms * 16 + 8 + g) * W_STRIDE;
                uint32_t ah0 = *(const uint32_t*)&Whs[r0 + kb + tig];
                uint32_t ah1 = *(const uint32_t*)&Whs[r1 + kb + tig];
                uint32_t ah2 = *(const uint32_t*)&Whs[r0 + kb + tig + 4];
                uint32_t ah3 = *(const uint32_t*)&Whs[r1 + kb + tig + 4];
                uint32_t al0 = *(const uint32_t*)&Wls[r0 + kb + tig];
                uint32_t al1 = *(const uint32_t*)&Wls[r1 + kb + tig];
                uint32_t al2 = *(const uint32_t*)&Wls[r0 + kb + tig + 4];
                uint32_t al3 = *(const uint32_t*)&Wls[r1 + kb + tig + 4];
                #pragma unroll
                for (int ns = 0; ns < 8; ns++) {
                    mma_f16(acc[ms][ns], ah0, ah1, ah2, ah3, bh[ns][0], bh[ns][1]);
                    mma_f16(acc[ms][ns], ah0, ah1, ah2, ah3, bl[ns][0], bl[ns][1]);
                    mma_f16(acc[ms][ns], al0, al1, al2, al3, bh[ns][0], bh[ns][1]);
                }
            }
        }

        // ---- epilogue: bias (+selu), float2 stores ----
        {
            float* baseV = g_V + (size_t)bi * NCH * HW + hw0;
            float* baseK = g_K + (size_t)bi * NCH * HW + hw0;
            float* baseQ = g_Q + (size_t)bi * NCH * HW + hw0;
            #pragma unroll
            for (int ms = 0; ms < 3; ms++) {
                #pragma unroll
                for (int half = 0; half < 2; half++) {
                    const int c = mrow0 + ms * 16 + g + half * 8;
                    const float bb = sbias[c];
                    #pragma unroll
                    for (int ns = 0; ns < 8; ns++) {
                        const int col = ncol0 + ns * 8 + tig * 2;
                        float v0 = acc[ms][ns][half * 2 + 0] + bb;
                        float v1 = acc[ms][ns][half * 2 + 1] + bb;
                        float2 o;
                        if (c < 64) {
                            o.x = v0; o.y = v1;
                            *(float2*)&baseV[(size_t)c * HW + col] = o;
                        } else if (c < 128) {
                            o.x = selu_f(v0); o.y = selu_f(v1);
                            *(float2*)&baseK[(size_t)(c - 64) * HW + col] = o;
                        } else {
                            o.x = selu_f(v0); o.y = selu_f(v1);
                            *(float2*)&baseQ[(size_t)(c - 128) * HW + col] = o;
                        }
                    }
                }
            }
        }

        __syncthreads();                   // all warps done reading Xh/Xl

        if (t + 1 < TPC) {
            CP_WAIT(0);
            __syncthreads();               // raw[(t+1)&1] fully arrived
            const float* rn = raw[(t + 1) & 1];
            #pragma unroll
            for (int j = 0; j < 4; j++) {
                int u = tid + j * 256;
                int kp = u >> 5, c4 = u & 31;
                float4 p0 = *(const float4*)&rn[(2 * kp) * RAW_STRIDE + c4 * 4];
                float4 p1 = *(const float4*)&rn[(2 * kp + 1) * RAW_STRIDE + c4 * 4];
                __half2 h0 = __floats2half2_rn(p0.x, p1.x);
                __half2 h1 = __floats2half2_rn(p0.y, p1.y);
                __half2 h2 = __floats2half2_rn(p0.z, p1.z);
                __half2 h3 = __floats2half2_rn(p0.w, p1.w);
                __half2 l0 = __floats2half2_rn(p0.x - __low2float(h0), p1.x - __high2float(h0));
                __half2 l1 = __floats2half2_rn(p0.y - __low2float(h1), p1.y - __high2float(h1));
                __half2 l2 = __floats2half2_rn(p0.z - __low2float(h2), p1.z - __high2float(h2));
                __half2 l3 = __floats2half2_rn(p0.w - __low2float(h3), p1.w - __high2float(h3));
                *(uint4*)&Xh[kp * X_STRIDE + c4 * 4] =
                    make_uint4(h2u(h0), h2u(h1), h2u(h2), h2u(h3));
                *(uint4*)&Xl[kp * X_STRIDE + c4 * 4] =
                    make_uint4(h2u(l0), h2u(l1), h2u(l2), h2u(l3));
            }
            __syncthreads();
        }
    }
}

// ---------------------------------------------------------------------------
// Kernel 2: gram + softmax.  One block per (b,c).
// ---------------------------------------------------------------------------
__global__ __launch_bounds__(128)
void gram_softmax_kernel()
{
    const int c = blockIdx.x;
    const int b = blockIdx.y;
    const int tid  = threadIdx.x;
    const int jg   = tid >> 5;
    const int lane = tid & 31;

    const float* Kb = g_K + ((size_t)b * ENS * NCH + c) * HW;
    const float* Qb = g_Q + ((size_t)b * ENS * NCH + c) * HW;

    float acc[16][4];
    #pragma unroll
    for (int i = 0; i < 16; i++)
        #pragma unroll
        for (int jj = 0; jj < 4; jj++) acc[i][jj] = 0.f;

    for (int it = 0; it < HW / 128; it++) {
        const int pos = (it * 32 + lane) * 4;
        float4 q[4];
        #pragma unroll
        for (int jj = 0; jj < 4; jj++) {
            int j = jg * 4 + jj;
            q[jj] = *(const float4*)&Qb[(size_t)j * NCH * HW + pos];
        }
        #pragma unroll
        for (int i = 0; i < 16; i++) {
            float4 k4 = *(const float4*)&Kb[(size_t)i * NCH * HW + pos];
            #pragma unroll
            for (int jj = 0; jj < 4; jj++) {
                acc[i][jj] += k4.x * q[jj].x + k4.y * q[jj].y
                            + k4.z * q[jj].z + k4.w * q[jj].w;
            }
        }
    }

    __shared__ float sdots[16][16];
    #pragma unroll
    for (int i = 0; i < 16; i++)
        #pragma unroll
        for (int jj = 0; jj < 4; jj++) {
            float v = acc[i][jj];
            #pragma unroll
            for (int off = 16; off > 0; off >>= 1)
                v += __shfl_xor_sync(0xffffffffu, v, off);
            if (lane == 0) sdots[i][jg * 4 + jj] = v;
        }
    __syncthreads();

    if (tid < 16) {
        const int j = tid;
        float m = -INFINITY;
        #pragma unroll
        for (int i = 0; i < 16; i++) m = fmaxf(m, sdots[i][j]);
        float e[16], s = 0.f;
        #pragma unroll
        for (int i = 0; i < 16; i++) { e[i] = expf(sdots[i][j] - m); s += e[i]; }
        const float inv = 1.f / s;
        #pragma unroll
        for (int i = 0; i < 16; i++)
            g_Wgt[(((size_t)b * NCH + c) * ENS + i) * ENS + j] = e[i] * inv;
    }
}

// ---------------------------------------------------------------------------
// Kernel 3: mix + selu.  (mean-centering cancels via softmax)
// ---------------------------------------------------------------------------
__global__ __launch_bounds__(256)
void mix_kernel(float* __restrict__ out)
{
    const int tile = blockIdx.x;
    const int c    = blockIdx.y;
    const int b    = blockIdx.z;
    const int tid  = threadIdx.x;

    __shared__ float ws[16][16];
    ws[tid >> 4][tid & 15] = g_Wgt[((size_t)b * NCH + c) * 256 + tid];
    __syncthreads();

    const int pos = tile * 512 + tid * 2;
    const float* Vb = g_V + ((size_t)b * ENS * NCH + c) * HW + pos;
    float*       ob = out + ((size_t)b * ENS * NCH + c) * HW + pos;

    float2 v[16];
    #pragma unroll
    for (int i = 0; i < 16; i++)
        v[i] = *(const float2*)&Vb[(size_t)i * NCH * HW];

    #pragma unroll
    for (int j = 0; j < 16; j++) {
        float sx = 0.f, sy = 0.f;
        #pragma unroll
        for (int i = 0; i < 16; i++) {
            float w = ws[i][j];
            sx += w * v[i].x;
            sy += w * v[i].y;
        }
        float2 o; o.x = selu_f(sx); o.y = selu_f(sy);
        *(float2*)&ob[(size_t)j * NCH * HW] = o;
    }
}

// ---------------------------------------------------------------------------
extern "C" void kernel_launch(void* const* d_in, const int* in_sizes, int n_in,
                              void* d_out, int out_size)
{
    const float* x  = (const float*)d_in[0];
    const float* Wv = (const float*)d_in[1];
    const float* bv = (const float*)d_in[2];
    const float* Wk = (const float*)d_in[3];
    const float* bk = (const float*)d_in[4];
    const float* Wq = (const float*)d_in[5];
    const float* bq = (const float*)d_in[6];
    float* out = (float*)d_out;

    cudaFuncSetAttribute(conv3_mma_kernel,
                         cudaFuncAttributeMaxDynamicSharedMemorySize, SMEM_BYTES);

    dim3 g1(NBI, (HW / 128) / TPC);   // (128, 8)
    conv3_mma_kernel<<<g1, 256, SMEM_BYTES>>>(x, Wv, bv, Wk, bk, Wq, bq);

    dim3 g2(NCH, BATCH);
    gram_softmax_kernel<<<g2, 128>>>();

    dim3 g3(HW / 512, NCH, BATCH);
    mix_kernel<<<g3, 256>>>(out);
}

// round 8
// speedup vs baseline: 2.7476x; 1.4913x over previous
#include <cuda_runtime.h>
#include <cuda_fp16.h>
#include <math.h>
#include <stdint.h>
#include <string.h>

// Problem dims
#define BATCH 8
#define ENS   16
#define NCIN  64
#define NCH   64
#define HW    4096
#define NBI   (BATCH*ENS)          // 128
#define NELEM ((size_t)NBI*NCH*HW) // 33,554,432

// Scratch (static device arrays -- allocation-free)
__device__ float g_V[NELEM];
__device__ float g_K[NELEM];
__device__ float g_Q[NELEM];
__device__ float g_Wgt[BATCH*NCH*ENS*ENS]; // softmaxed weights [b,c,i,j]

__device__ __forceinline__ float selu_f(float x) {
    const float scale = 1.0507009873554805f;
    const float alpha = 1.6732632423543772f;
    return x > 0.f ? scale * x : scale * alpha * expm1f(x);
}

__device__ __forceinline__ uint32_t h2u(__half2 v) {
    uint32_t r;
    memcpy(&r, &v, sizeof(r));
    return r;
}

__device__ __forceinline__ uint32_t smem_u32(const void* p) {
    return (uint32_t)__cvta_generic_to_shared(p);
}
__device__ __forceinline__ void cp16(void* dst_smem, const void* src) {
    uint32_t d = smem_u32(dst_smem);
    asm volatile("cp.async.cg.shared.global [%0], [%1], 16;" :: "r"(d), "l"(src));
}
#define CP_COMMIT()  asm volatile("cp.async.commit_group;" ::: "memory")
#define CP_WAIT(n)   asm volatile("cp.async.wait_group %0;" :: "n"(n) : "memory")

// fp16 MMA m16n8k16 (baseline PTX, valid on sm_103 non-'a' target)
__device__ __forceinline__ void mma_f16(float* c,
                                        uint32_t a0, uint32_t a1, uint32_t a2, uint32_t a3,
                                        uint32_t b0, uint32_t b1)
{
    asm volatile(
        "mma.sync.aligned.m16n8k16.row.col.f32.f16.f16.f32 "
        "{%0,%1,%2,%3}, {%4,%5,%6,%7}, {%8,%9}, {%0,%1,%2,%3};"
        : "+f"(c[0]), "+f"(c[1]), "+f"(c[2]), "+f"(c[3])
        : "r"(a0), "r"(a1), "r"(a2), "r"(a3), "r"(b0), "r"(b1));
}

// ===========================================================================
// Kernel 1: fused 3-conv via FP16-split (2-way) mma.sync m16n8k16.
// Per (b,i): Out[192 ch, 4096 hw] = W3[192,64] @ X[64,4096]
// W = Wh + Wl, X = Xh + Xl (fp16 halves). D = Wh*Xh + Wh*Xl + Wl*Xh.
// CTA: 512 thr (16 warps, 4m x 4n), tile 192 x 128 hw, TPC hw-tiles per CTA.
// Xh/Xl double-buffered so conversion of tile t+1 overlaps nothing-critical
// and only 2 __syncthreads per tile are needed.
// ===========================================================================
#define THREADS    512
#define TPC        4
#define W_STRIDE   36    // half2 units per W row (32 kpairs + pad)
#define X_STRIDE   136   // half2 units per X kpair-row (128 cols + pad)
#define RAW_STRIDE 132   // float units per raw X row (128 + pad)

// SMEM byte offsets
#define OFF_WH    0                                  // 192*36*4 = 27648
#define OFF_WL    (OFF_WH  + 192*W_STRIDE*4)         // 27648
#define OFF_RAW   (OFF_WL  + 192*W_STRIDE*4)         // 55296; 64*132*4 = 33792
#define OFF_XH0   (OFF_RAW + 64*RAW_STRIDE*4)        // 89088;  32*136*4 = 17408
#define OFF_XL0   (OFF_XH0 + 32*X_STRIDE*4)          // 106496
#define OFF_XH1   (OFF_XL0 + 32*X_STRIDE*4)          // 123904
#define OFF_XL1   (OFF_XH1 + 32*X_STRIDE*4)          // 141312
#define OFF_BIAS  (OFF_XL1 + 32*X_STRIDE*4)          // 158720
#define SMEM_BYTES (OFF_BIAS + 192*4)                // 159488

// Convert one raw fp32 tile [64 cin x 128 hw] -> kpair-packed fp16 hi/lo
__device__ __forceinline__ void convert_tile(const float* __restrict__ rawp,
                                             __half2* __restrict__ Xh,
                                             __half2* __restrict__ Xl,
                                             int tid)
{
    #pragma unroll
    for (int j = 0; j < 2; j++) {
        int u = tid + j * THREADS;         // 1024 (kp, c4) units
        int kp = u >> 5, c4 = u & 31;
        float4 p0 = *(const float4*)&rawp[(2 * kp) * RAW_STRIDE + c4 * 4];
        float4 p1 = *(const float4*)&rawp[(2 * kp + 1) * RAW_STRIDE + c4 * 4];
        __half2 h0 = __floats2half2_rn(p0.x, p1.x);
        __half2 h1 = __floats2half2_rn(p0.y, p1.y);
        __half2 h2 = __floats2half2_rn(p0.z, p1.z);
        __half2 h3 = __floats2half2_rn(p0.w, p1.w);
        __half2 l0 = __floats2half2_rn(p0.x - __low2float(h0), p1.x - __high2float(h0));
        __half2 l1 = __floats2half2_rn(p0.y - __low2float(h1), p1.y - __high2float(h1));
        __half2 l2 = __floats2half2_rn(p0.z - __low2float(h2), p1.z - __high2float(h2));
        __half2 l3 = __floats2half2_rn(p0.w - __low2float(h3), p1.w - __high2float(h3));
        *(uint4*)&Xh[kp * X_STRIDE + c4 * 4] =
            make_uint4(h2u(h0), h2u(h1), h2u(h2), h2u(h3));
        *(uint4*)&Xl[kp * X_STRIDE + c4 * 4] =
            make_uint4(h2u(l0), h2u(l1), h2u(l2), h2u(l3));
    }
}

__global__ __launch_bounds__(THREADS, 1)
void conv3_mma_kernel(const float* __restrict__ x,
                      const float* __restrict__ Wv, const float* __restrict__ bv,
                      const float* __restrict__ Wk, const float* __restrict__ bk,
                      const float* __restrict__ Wq, const float* __restrict__ bq)
{
    extern __shared__ char smem[];
    __half2* Whs = (__half2*)(smem + OFF_WH);
    __half2* Wls = (__half2*)(smem + OFF_WL);
    float*   rawp = (float*)(smem + OFF_RAW);
    __half2* XhB[2] = { (__half2*)(smem + OFF_XH0), (__half2*)(smem + OFF_XH1) };
    __half2* XlB[2] = { (__half2*)(smem + OFF_XL0), (__half2*)(smem + OFF_XL1) };
    float*   sbias = (float*)(smem + OFF_BIAS);

    const int tid  = threadIdx.x;
    const int wid  = tid >> 5;
    const int lane = tid & 31;
    const int g    = lane >> 2;     // groupID
    const int tig  = lane & 3;      // threadID_in_group

    const int bi = blockIdx.x;      // 0..127
    const int tg = blockIdx.y;      // 0..7
    const float* xb = x + (size_t)bi * NCIN * HW;

    // ---- stage tile0 raw X via cp.async ----
    {
        const int hw0 = tg * TPC * 128;
        #pragma unroll
        for (int j = 0; j < 4; j++) {
            int idx = tid + j * THREADS;      // 2048 float4s
            int cin = idx >> 5, c4 = idx & 31;
            cp16(&rawp[cin * RAW_STRIDE + c4 * 4],
                 xb + (size_t)cin * HW + hw0 + c4 * 4);
        }
        CP_COMMIT();
    }

    // ---- W3 -> fp16 hi/lo in SMEM (kpair-packed); bias ----
    if (tid < 192) {
        sbias[tid] = tid < 64 ? bv[tid] : (tid < 128 ? bk[tid - 64] : bq[tid - 128]);
    }
    #pragma unroll
    for (int j = 0; j < 12; j++) {
        int idx = tid + j * THREADS;          // 6144 kpairs
        int n = idx >> 5, kp = idx & 31;
        const float* Wsrc = n < 64 ? &Wv[n * NCIN] :
                            n < 128 ? &Wk[(n - 64) * NCIN] : &Wq[(n - 128) * NCIN];
        float w0 = Wsrc[kp * 2], w1 = Wsrc[kp * 2 + 1];
        __half2 h = __floats2half2_rn(w0, w1);
        __half2 l = __floats2half2_rn(w0 - __low2float(h), w1 - __high2float(h));
        Whs[n * W_STRIDE + kp] = h;
        Wls[n * W_STRIDE + kp] = l;
    }

    CP_WAIT(0);
    __syncthreads();
    convert_tile(rawp, XhB[0], XlB[0], tid);
    __syncthreads();

    const int mrow0 = (wid & 3) * 48;   // warp channel-rows base (3 x m16)
    const int ncol0 = (wid >> 2) * 32;  // warp hw-cols base (4 x n8)

    for (int t = 0; t < TPC; t++) {
        const int hw0 = (tg * TPC + t) * 128;

        // prefetch next raw tile (overlaps with MMA below)
        if (t + 1 < TPC) {
            const int hwn = hw0 + 128;
            #pragma unroll
            for (int j = 0; j < 4; j++) {
                int idx = tid + j * THREADS;
                int cin = idx >> 5, c4 = idx & 31;
                cp16(&rawp[cin * RAW_STRIDE + c4 * 4],
                     xb + (size_t)cin * HW + hwn + c4 * 4);
            }
            CP_COMMIT();
        }

        const __half2* Xh = XhB[t & 1];
        const __half2* Xl = XlB[t & 1];

        // ---- MMA: 4 ksteps (K=16) x 3 m-blocks x 4 n-blocks x 3 products ----
        float acc[3][4][4];
        #pragma unroll
        for (int ms = 0; ms < 3; ms++)
            #pragma unroll
            for (int ns = 0; ns < 4; ns++)
                #pragma unroll
                for (int q = 0; q < 4; q++) acc[ms][ns][q] = 0.f;

        #pragma unroll
        for (int ks = 0; ks < 4; ks++) {
            const int kb = ks * 8;
            uint32_t bh[4][2], bl[4][2];
            #pragma unroll
            for (int ns = 0; ns < 4; ns++) {
                const int col = ncol0 + ns * 8 + g;
                bh[ns][0] = *(const uint32_t*)&Xh[(kb + tig) * X_STRIDE + col];
                bh[ns][1] = *(const uint32_t*)&Xh[(kb + tig + 4) * X_STRIDE + col];
                bl[ns][0] = *(const uint32_t*)&Xl[(kb + tig) * X_STRIDE + col];
                bl[ns][1] = *(const uint32_t*)&Xl[(kb + tig + 4) * X_STRIDE + col];
            }
            #pragma unroll
            for (int ms = 0; ms < 3; ms++) {
                const int r0 = (mrow0 + ms * 16 + g) * W_STRIDE;
                const int r1 = (mrow0 + ms * 16 + 8 + g) * W_STRIDE;
                uint32_t ah0 = *(const uint32_t*)&Whs[r0 + kb + tig];
                uint32_t ah1 = *(const uint32_t*)&Whs[r1 + kb + tig];
                uint32_t ah2 = *(const uint32_t*)&Whs[r0 + kb + tig + 4];
                uint32_t ah3 = *(const uint32_t*)&Whs[r1 + kb + tig + 4];
                uint32_t al0 = *(const uint32_t*)&Wls[r0 + kb + tig];
                uint32_t al1 = *(const uint32_t*)&Wls[r1 + kb + tig];
                uint32_t al2 = *(const uint32_t*)&Wls[r0 + kb + tig + 4];
                uint32_t al3 = *(const uint32_t*)&Wls[r1 + kb + tig + 4];
                #pragma unroll
                for (int ns = 0; ns < 4; ns++) {
                    mma_f16(acc[ms][ns], ah0, ah1, ah2, ah3, bh[ns][0], bh[ns][1]);
                    mma_f16(acc[ms][ns], ah0, ah1, ah2, ah3, bl[ns][0], bl[ns][1]);
                    mma_f16(acc[ms][ns], al0, al1, al2, al3, bh[ns][0], bh[ns][1]);
                }
            }
        }

        // ---- epilogue: bias (+selu), float2 stores ----
        {
            float* baseV = g_V + (size_t)bi * NCH * HW + hw0;
            float* baseK = g_K + (size_t)bi * NCH * HW + hw0;
            float* baseQ = g_Q + (size_t)bi * NCH * HW + hw0;
            #pragma unroll
            for (int ms = 0; ms < 3; ms++) {
                #pragma unroll
                for (int half = 0; half < 2; half++) {
                    const int c = mrow0 + ms * 16 + g + half * 8;
                    const float bb = sbias[c];
                    #pragma unroll
                    for (int ns = 0; ns < 4; ns++) {
                        const int col = ncol0 + ns * 8 + tig * 2;
                        float v0 = acc[ms][ns][half * 2 + 0] + bb;
                        float v1 = acc[ms][ns][half * 2 + 1] + bb;
                        float2 o;
                        if (c < 64) {
                            o.x = v0; o.y = v1;
                            *(float2*)&baseV[(size_t)c * HW + col] = o;
                        } else if (c < 128) {
                            o.x = selu_f(v0); o.y = selu_f(v1);
                            *(float2*)&baseK[(size_t)(c - 64) * HW + col] = o;
                        } else {
                            o.x = selu_f(v0); o.y = selu_f(v1);
                            *(float2*)&baseQ[(size_t)(c - 128) * HW + col] = o;
                        }
                    }
                }
            }
        }

        if (t + 1 < TPC) {
            CP_WAIT(0);
            __syncthreads();               // raw(t+1) arrived, all warps past MMA(t)
            convert_tile(rawp, XhB[(t + 1) & 1], XlB[(t + 1) & 1], tid);
            __syncthreads();               // Xh/Xl[(t+1)&1] ready for next MMA
        }
    }
}

// ---------------------------------------------------------------------------
// Kernel 2: gram + softmax.  One block per (b,c).
// ---------------------------------------------------------------------------
__global__ __launch_bounds__(128)
void gram_softmax_kernel()
{
    const int c = blockIdx.x;
    const int b = blockIdx.y;
    const int tid  = threadIdx.x;
    const int jg   = tid >> 5;
    const int lane = tid & 31;

    const float* Kb = g_K + ((size_t)b * ENS * NCH + c) * HW;
    const float* Qb = g_Q + ((size_t)b * ENS * NCH + c) * HW;

    float acc[16][4];
    #pragma unroll
    for (int i = 0; i < 16; i++)
        #pragma unroll
        for (int jj = 0; jj < 4; jj++) acc[i][jj] = 0.f;

    for (int it = 0; it < HW / 128; it++) {
        const int pos = (it * 32 + lane) * 4;
        float4 q[4];
        #pragma unroll
        for (int jj = 0; jj < 4; jj++) {
            int j = jg * 4 + jj;
            q[jj] = *(const float4*)&Qb[(size_t)j * NCH * HW + pos];
        }
        #pragma unroll
        for (int i = 0; i < 16; i++) {
            float4 k4 = *(const float4*)&Kb[(size_t)i * NCH * HW + pos];
            #pragma unroll
            for (int jj = 0; jj < 4; jj++) {
                acc[i][jj] += k4.x * q[jj].x + k4.y * q[jj].y
                            + k4.z * q[jj].z + k4.w * q[jj].w;
            }
        }
    }

    __shared__ float sdots[16][16];
    #pragma unroll
    for (int i = 0; i < 16; i++)
        #pragma unroll
        for (int jj = 0; jj < 4; jj++) {
            float v = acc[i][jj];
            #pragma unroll
            for (int off = 16; off > 0; off >>= 1)
                v += __shfl_xor_sync(0xffffffffu, v, off);
            if (lane == 0) sdots[i][jg * 4 + jj] = v;
        }
    __syncthreads();

    if (tid < 16) {
        const int j = tid;
        float m = -INFINITY;
        #pragma unroll
        for (int i = 0; i < 16; i++) m = fmaxf(m, sdots[i][j]);
        float e[16], s = 0.f;
        #pragma unroll
        for (int i = 0; i < 16; i++) { e[i] = expf(sdots[i][j] - m); s += e[i]; }
        const float inv = 1.f / s;
        #pragma unroll
        for (int i = 0; i < 16; i++)
            g_Wgt[(((size_t)b * NCH + c) * ENS + i) * ENS + j] = e[i] * inv;
    }
}

// ---------------------------------------------------------------------------
// Kernel 3: mix + selu.  (mean-centering cancels via softmax)
// ---------------------------------------------------------------------------
__global__ __launch_bounds__(256)
void mix_kernel(float* __restrict__ out)
{
    const int tile = blockIdx.x;
    const int c    = blockIdx.y;
    const int b    = blockIdx.z;
    const int tid  = threadIdx.x;

    __shared__ float ws[16][16];
    ws[tid >> 4][tid & 15] = g_Wgt[((size_t)b * NCH + c) * 256 + tid];
    __syncthreads();

    const int pos = tile * 512 + tid * 2;
    const float* Vb = g_V + ((size_t)b * ENS * NCH + c) * HW + pos;
    float*       ob = out + ((size_t)b * ENS * NCH + c) * HW + pos;

    float2 v[16];
    #pragma unroll
    for (int i = 0; i < 16; i++)
        v[i] = *(const float2*)&Vb[(size_t)i * NCH * HW];

    #pragma unroll
    for (int j = 0; j < 16; j++) {
        float sx = 0.f, sy = 0.f;
        #pragma unroll
        for (int i = 0; i < 16; i++) {
            float w = ws[i][j];
            sx += w * v[i].x;
            sy += w * v[i].y;
        }
        float2 o; o.x = selu_f(sx); o.y = selu_f(sy);
        *(float2*)&ob[(size_t)j * NCH * HW] = o;
    }
}

// ---------------------------------------------------------------------------
extern "C" void kernel_launch(void* const* d_in, const int* in_sizes, int n_in,
                              void* d_out, int out_size)
{
    const float* x  = (const float*)d_in[0];
    const float* Wv = (const float*)d_in[1];
    const float* bv = (const float*)d_in[2];
    const float* Wk = (const float*)d_in[3];
    const float* bk = (const float*)d_in[4];
    const float* Wq = (const float*)d_in[5];
    const float* bq = (const float*)d_in[6];
    float* out = (float*)d_out;

    cudaFuncSetAttribute(conv3_mma_kernel,
                         cudaFuncAttributeMaxDynamicSharedMemorySize, SMEM_BYTES);

    dim3 g1(NBI, (HW / 128) / TPC);   // (128, 8)
    conv3_mma_kernel<<<g1, THREADS, SMEM_BYTES>>>(x, Wv, bv, Wk, bk, Wq, bq);

    dim3 g2(NCH, BATCH);
    gram_softmax_kernel<<<g2, 128>>>();

    dim3 g3(HW / 512, NCH, BATCH);
    mix_kernel<<<g3, 256>>>(out);
}